// round 12
// baseline (speedup 1.0000x reference)
#include <cuda_runtime.h>
#include <cuda_fp16.h>
#include <cstdint>
#include <cstddef>

#define N_NODES 50000
#define N_EDGES 800000
#define CAP 96                          // bucket capacity per node (max in-deg ~38 expected)

// ---------------- scratch ----------------
__device__ int    g_deg[N_NODES];
__device__ float  g_norm[N_NODES];
__device__ int    g_bucket[N_NODES * CAP];   // 19.2 MB
__device__ __align__(16) __half g_xh[N_NODES * 128];   // fp16 features
__device__ __align__(16) __half g_Y[N_NODES * 192];    // layer-1 GEMM output (3 planes of 64)
__device__ __align__(16) __half g_t1h[N_NODES * 64];
__device__ __align__(16) __half g_t2h[N_NODES * 64];
__device__ __align__(16) __half g_h1h[N_NODES * 64];
__device__ __align__(16) __half g_h2h[N_NODES * 64];

// ---------------- feature convert ----------------
__global__ void cvt_kernel(const float* __restrict__ X) {
    int i = blockIdx.x * blockDim.x + threadIdx.x;   // over half2 pairs
    if (i < N_NODES * 64) {
        float2 v = ((const float2*)X)[i];
        ((__half2*)g_xh)[i] = __float22half2_rn(v);
    }
}

// ---------------- graph build: single edge pass into buckets ----------------
__global__ void zero_deg_kernel() {
    int i = blockIdx.x * blockDim.x + threadIdx.x;
    if (i < N_NODES) g_deg[i] = 0;
}

__global__ void fill_bucket_kernel(const int* __restrict__ src, const int* __restrict__ dst) {
    int i = blockIdx.x * blockDim.x + threadIdx.x;   // groups of 4 edges
    if (i * 4 + 4 <= N_EDGES) {
        int4 d = ((const int4*)dst)[i];
        int4 s = ((const int4*)src)[i];
        int p0 = atomicAdd(&g_deg[d.x], 1);
        int p1 = atomicAdd(&g_deg[d.y], 1);
        int p2 = atomicAdd(&g_deg[d.z], 1);
        int p3 = atomicAdd(&g_deg[d.w], 1);
        if (p0 < CAP) g_bucket[d.x * CAP + p0] = s.x;
        if (p1 < CAP) g_bucket[d.y * CAP + p1] = s.y;
        if (p2 < CAP) g_bucket[d.z * CAP + p2] = s.z;
        if (p3 < CAP) g_bucket[d.w * CAP + p3] = s.w;
    }
}

__global__ void norm_kernel() {
    int i = blockIdx.x * blockDim.x + threadIdx.x;
    if (i < N_NODES) {
        float d = (float)g_deg[i];
        g_norm[i] = rsqrtf(d < 1.0f ? 1.0f : d);
    }
}

// ---------------- propagation (64 cols, 4 nodes/warp, fully predicated 8-edge loop) ----------------
// out[n] = (addt ? addt[n] : 0) + norm[n] * sum_{e in in(n)} X[src_e]*norm[src_e]
__global__ void prop64(const __half* __restrict__ X, int sx,
                       const __half* __restrict__ addt, int sa,
                       __half* __restrict__ out, int so) {
    int gwarp = (blockIdx.x * blockDim.x + threadIdx.x) >> 5;
    int lane = threadIdx.x & 31;
    int node = gwarp * 4 + (lane >> 3);
    int sub  = lane & 7;
    if (node >= N_NODES) return;
    int dg = g_deg[node];
    if (dg > CAP) dg = CAP;
    const int* bkt = g_bucket + node * CAP;

    float acc[8];
    #pragma unroll
    for (int i = 0; i < 8; i++) acc[i] = 0.f;

    for (int e = 0; e < dg; e += 8) {
        int s[8];
        float nn[8];
        #pragma unroll
        for (int j = 0; j < 8; j++) {
            int idx = e + j;
            int cl = idx < dg ? idx : dg - 1;          // dg>=1 inside loop
            s[j] = bkt[cl];
            nn[j] = idx < dg ? g_norm[s[j]] : 0.f;     // zero-weight OOB
        }
        uint4 v[8];
        #pragma unroll
        for (int j = 0; j < 8; j++)
            v[j] = *(const uint4*)(X + (size_t)s[j] * sx + sub * 8);
        #pragma unroll
        for (int j = 0; j < 8; j++) {
            float2 f0 = __half22float2(*(const __half2*)&v[j].x);
            float2 f1 = __half22float2(*(const __half2*)&v[j].y);
            float2 f2 = __half22float2(*(const __half2*)&v[j].z);
            float2 f3 = __half22float2(*(const __half2*)&v[j].w);
            acc[0] += f0.x * nn[j]; acc[1] += f0.y * nn[j];
            acc[2] += f1.x * nn[j]; acc[3] += f1.y * nn[j];
            acc[4] += f2.x * nn[j]; acc[5] += f2.y * nn[j];
            acc[6] += f3.x * nn[j]; acc[7] += f3.y * nn[j];
        }
    }

    float m = g_norm[node];
    float r[8];
    #pragma unroll
    for (int i = 0; i < 8; i++) r[i] = m * acc[i];
    if (addt) {
        uint4 a = *(const uint4*)(addt + (size_t)node * sa + sub * 8);
        float2 f0 = __half22float2(*(const __half2*)&a.x);
        float2 f1 = __half22float2(*(const __half2*)&a.y);
        float2 f2 = __half22float2(*(const __half2*)&a.z);
        float2 f3 = __half22float2(*(const __half2*)&a.w);
        r[0] += f0.x; r[1] += f0.y; r[2] += f1.x; r[3] += f1.y;
        r[4] += f2.x; r[5] += f2.y; r[6] += f3.x; r[7] += f3.y;
    }
    uint4 w;
    *(__half2*)&w.x = __floats2half2_rn(r[0], r[1]);
    *(__half2*)&w.y = __floats2half2_rn(r[2], r[3]);
    *(__half2*)&w.z = __floats2half2_rn(r[4], r[5]);
    *(__half2*)&w.w = __floats2half2_rn(r[6], r[7]);
    *(uint4*)(out + (size_t)node * so + sub * 8) = w;
}

// ---------------- mma helper ----------------
__device__ __forceinline__ void mma_f16(float* c, const uint32_t* a, uint32_t b0, uint32_t b1) {
    asm volatile(
        "mma.sync.aligned.m16n8k16.row.col.f32.f16.f16.f32 "
        "{%0,%1,%2,%3}, {%4,%5,%6,%7}, {%8,%9}, {%0,%1,%2,%3};"
        : "+f"(c[0]), "+f"(c[1]), "+f"(c[2]), "+f"(c[3])
        : "r"(a[0]), "r"(a[1]), "r"(a[2]), "r"(a[3]), "r"(b0), "r"(b1));
}

// ---------------- Layer-1 commuted GEMM: Y[50k,192] = X @ foldW ----------------
// blockIdx.y = plane (0: W0-W2 +bias, 1: -W1, 2: 2*W2); 64 cols per plane → NT=8.
template <int F, int FTOT>
__global__ void gemmY_kernel(const __half* __restrict__ X,
                             const float* __restrict__ W,      // [3F, 64]
                             const float* __restrict__ bias,   // [64]
                             __half* __restrict__ Y) {
    constexpr int NT  = 8;
    constexpr int LDK = F + 2;
    __shared__ alignas(16) __half Ws[64 * LDK];   // Ws[col_local][k]

    int tid  = threadIdx.x;
    int warp = tid >> 5;
    int lane = tid & 31;
    int grp  = lane >> 2;
    int qid  = lane & 3;
    int plane = blockIdx.y;
    int colbase = plane * 64;
    int r0 = blockIdx.x * 256 + warp * 32;

    for (int i = tid; i < 64 * F; i += 256) {
        int k  = i / 64;
        int cc = i - k * 64;
        float v;
        if (plane == 0)      v = W[k * 64 + cc] - W[(2 * F + k) * 64 + cc];
        else if (plane == 1) v = -W[(F + k) * 64 + cc];
        else                 v = 2.0f * W[(2 * F + k) * 64 + cc];
        Ws[cc * LDK + k] = __float2half_rn(v);
    }
    __syncthreads();

    float c[2][NT][4];
    #pragma unroll
    for (int t = 0; t < 2; t++)
        #pragma unroll
        for (int n = 0; n < NT; n++)
            #pragma unroll
            for (int j = 0; j < 4; j++) c[t][n][j] = 0.f;

    int ra0 = r0 + grp;       if (ra0 >= N_NODES) ra0 = N_NODES - 1;
    int ra1 = r0 + grp + 8;   if (ra1 >= N_NODES) ra1 = N_NODES - 1;
    int ra2 = r0 + grp + 16;  if (ra2 >= N_NODES) ra2 = N_NODES - 1;
    int ra3 = r0 + grp + 24;  if (ra3 >= N_NODES) ra3 = N_NODES - 1;
    const __half* p0 = X + (size_t)ra0 * F;
    const __half* p1 = X + (size_t)ra1 * F;
    const __half* p2 = X + (size_t)ra2 * F;
    const __half* p3 = X + (size_t)ra3 * F;

    for (int k0 = 0; k0 < F; k0 += 16) {
        int ka = k0 + 2 * qid;
        uint32_t A0[4], A1[4];
        A0[0] = *(const uint32_t*)(p0 + ka);
        A0[1] = *(const uint32_t*)(p1 + ka);
        A0[2] = *(const uint32_t*)(p0 + ka + 8);
        A0[3] = *(const uint32_t*)(p1 + ka + 8);
        A1[0] = *(const uint32_t*)(p2 + ka);
        A1[1] = *(const uint32_t*)(p3 + ka);
        A1[2] = *(const uint32_t*)(p2 + ka + 8);
        A1[3] = *(const uint32_t*)(p3 + ka + 8);

        #pragma unroll
        for (int n = 0; n < NT; n++) {
            const __half* wb = Ws + (n * 8 + grp) * LDK + ka;
            uint32_t b0 = *(const uint32_t*)(wb);
            uint32_t b1 = *(const uint32_t*)(wb + 8);
            mma_f16(c[0][n], A0, b0, b1);
            mma_f16(c[1][n], A1, b0, b1);
        }
    }

    #pragma unroll
    for (int t = 0; t < 2; t++) {
        int rA = r0 + t * 16 + grp;
        int rB = rA + 8;
        #pragma unroll
        for (int n = 0; n < NT; n++) {
            int cl = n * 8 + qid * 2;
            float bx = (plane == 0) ? bias[cl] : 0.f;
            float by = (plane == 0) ? bias[cl + 1] : 0.f;
            int col = colbase + cl;
            if (rA < N_NODES) {
                __half2 v = __floats2half2_rn(c[t][n][0] + bx, c[t][n][1] + by);
                *(__half2*)(Y + (size_t)rA * FTOT + col) = v;
            }
            if (rB < N_NODES) {
                __half2 v = __floats2half2_rn(c[t][n][2] + bx, c[t][n][3] + by);
                *(__half2*)(Y + (size_t)rB * FTOT + col) = v;
            }
        }
    }
}

// ---------------- 3-input GEMM (layers 2,3) ----------------
template <int F, int FOUT, typename OutT>
__global__ void gemm3_mma_kernel(const __half* __restrict__ X0,
                                 const __half* __restrict__ X1,
                                 const __half* __restrict__ X2,
                                 const float* __restrict__ W,
                                 const float* __restrict__ bias,
                                 OutT* __restrict__ out) {
    constexpr int NT  = FOUT / 8;
    constexpr int LDK = F + 2;
    __shared__ alignas(16) __half Ws[FOUT * LDK];

    int tid  = threadIdx.x;
    int warp = tid >> 5;
    int lane = tid & 31;
    int grp  = lane >> 2;
    int qid  = lane & 3;
    int r0 = blockIdx.x * 256 + warp * 32;

    float c[2][NT][4];
    #pragma unroll
    for (int t = 0; t < 2; t++)
        #pragma unroll
        for (int n = 0; n < NT; n++)
            #pragma unroll
            for (int j = 0; j < 4; j++) c[t][n][j] = 0.f;

    const __half* segs[3] = {X0, X1, X2};

    int ra0 = r0 + grp;       if (ra0 >= N_NODES) ra0 = N_NODES - 1;
    int ra1 = r0 + grp + 8;   if (ra1 >= N_NODES) ra1 = N_NODES - 1;
    int ra2 = r0 + grp + 16;  if (ra2 >= N_NODES) ra2 = N_NODES - 1;
    int ra3 = r0 + grp + 24;  if (ra3 >= N_NODES) ra3 = N_NODES - 1;

    #pragma unroll
    for (int seg = 0; seg < 3; ++seg) {
        __syncthreads();
        for (int i = tid; i < F * FOUT; i += 256) {
            int k = i / FOUT, col = i - k * FOUT;
            float v;
            if (seg == 0)      v = W[i] - W[2 * F * FOUT + i];
            else if (seg == 1) v = -W[F * FOUT + i];
            else               v = 2.0f * W[2 * F * FOUT + i];
            Ws[col * LDK + k] = __float2half_rn(v);
        }
        __syncthreads();

        const __half* X  = segs[seg];
        const __half* p0 = X + (size_t)ra0 * F;
        const __half* p1 = X + (size_t)ra1 * F;
        const __half* p2 = X + (size_t)ra2 * F;
        const __half* p3 = X + (size_t)ra3 * F;

        for (int k0 = 0; k0 < F; k0 += 16) {
            int ka = k0 + 2 * qid;
            uint32_t A0[4], A1[4];
            A0[0] = *(const uint32_t*)(p0 + ka);
            A0[1] = *(const uint32_t*)(p1 + ka);
            A0[2] = *(const uint32_t*)(p0 + ka + 8);
            A0[3] = *(const uint32_t*)(p1 + ka + 8);
            A1[0] = *(const uint32_t*)(p2 + ka);
            A1[1] = *(const uint32_t*)(p3 + ka);
            A1[2] = *(const uint32_t*)(p2 + ka + 8);
            A1[3] = *(const uint32_t*)(p3 + ka + 8);

            #pragma unroll
            for (int n = 0; n < NT; n++) {
                const __half* wb = Ws + (n * 8 + grp) * LDK + ka;
                uint32_t b0 = *(const uint32_t*)(wb);
                uint32_t b1 = *(const uint32_t*)(wb + 8);
                mma_f16(c[0][n], A0, b0, b1);
                mma_f16(c[1][n], A1, b0, b1);
            }
        }
    }

    #pragma unroll
    for (int t = 0; t < 2; t++) {
        int rA = r0 + t * 16 + grp;
        int rB = rA + 8;
        #pragma unroll
        for (int n = 0; n < NT; n++) {
            int col = n * 8 + qid * 2;
            float bx = bias[col], by = bias[col + 1];
            if (rA < N_NODES) {
                if constexpr (sizeof(OutT) == 2) {
                    __half2 v = __floats2half2_rn(c[t][n][0] + bx, c[t][n][1] + by);
                    *(__half2*)((__half*)out + (size_t)rA * FOUT + col) = v;
                } else {
                    float2 v = make_float2(c[t][n][0] + bx, c[t][n][1] + by);
                    *(float2*)((float*)out + (size_t)rA * FOUT + col) = v;
                }
            }
            if (rB < N_NODES) {
                if constexpr (sizeof(OutT) == 2) {
                    __half2 v = __floats2half2_rn(c[t][n][2] + bx, c[t][n][3] + by);
                    *(__half2*)((__half*)out + (size_t)rB * FOUT + col) = v;
                } else {
                    float2 v = make_float2(c[t][n][2] + bx, c[t][n][3] + by);
                    *(float2*)((float*)out + (size_t)rB * FOUT + col) = v;
                }
            }
        }
    }
}

// ---------------- host ----------------
extern "C" void kernel_launch(void* const* d_in, const int* in_sizes, int n_in,
                              void* d_out, int out_size) {
    const float* features = (const float*)d_in[0];   // [50000,128]
    const int*   src      = (const int*)d_in[1];     // [800000]
    const int*   dst      = (const int*)d_in[2];     // [800000]
    const float* W1       = (const float*)d_in[3];   // [384,64]
    const float* b1       = (const float*)d_in[4];   // [64]
    const float* W2       = (const float*)d_in[5];   // [192,64]
    const float* b2       = (const float*)d_in[6];   // [64]
    const float* W3       = (const float*)d_in[7];   // [192,40]
    const float* b3       = (const float*)d_in[8];   // [40]
    float* out            = (float*)d_out;           // [50000,40]

    __half *xh, *Y, *t1, *t2, *h1, *h2;
    cudaGetSymbolAddress((void**)&xh, g_xh);
    cudaGetSymbolAddress((void**)&Y,  g_Y);
    cudaGetSymbolAddress((void**)&t1, g_t1h);
    cudaGetSymbolAddress((void**)&t2, g_t2h);
    cudaGetSymbolAddress((void**)&h1, g_h1h);
    cudaGetSymbolAddress((void**)&h2, g_h2h);

    static cudaStream_t sB = nullptr;
    static cudaEvent_t evFork = nullptr, evJoin = nullptr;
    if (!sB) {
        cudaStreamCreateWithFlags(&sB, cudaStreamNonBlocking);
        cudaEventCreateWithFlags(&evFork, cudaEventDisableTiming);
        cudaEventCreateWithFlags(&evJoin, cudaEventDisableTiming);
    }

    const int PROP_BLK  = 256;                        // 8 warps x 4 nodes = 32 nodes/block
    const int PROP_GRID = (N_NODES + 31) / 32;
    const int GEMM_GRID = (N_NODES + 255) / 256;

    // ---- fork: bucket build on sB, cvt+gemmY on main stream ----
    cudaEventRecord(evFork, 0);
    cudaStreamWaitEvent(sB, evFork, 0);

    zero_deg_kernel<<<(N_NODES + 255) / 256, 256, 0, sB>>>();
    fill_bucket_kernel<<<(N_EDGES / 4 + 255) / 256, 256, 0, sB>>>(src, dst);
    norm_kernel<<<(N_NODES + 255) / 256, 256, 0, sB>>>();
    cudaEventRecord(evJoin, sB);

    cvt_kernel<<<(N_NODES * 64 + 255) / 256, 256>>>(features);
    {
        dim3 grid(GEMM_GRID, 3);                      // 3 planes of 64 cols
        gemmY_kernel<128, 192><<<grid, 256>>>(xh, W1, b1, Y);
    }
    cudaStreamWaitEvent(0, evJoin, 0);

    // ---- Layer 1 (commuted): t1 = Y1 + P Y2; h1 = Y0 + P t1 ----
    prop64<<<PROP_GRID, PROP_BLK>>>(Y + 128, 192, Y + 64, 192, t1, 64);
    prop64<<<PROP_GRID, PROP_BLK>>>(t1, 64, Y, 192, h1, 64);

    // ---- Layer 2: U1 = P h1, U2 = P U1; gemm3 folded ----
    prop64<<<PROP_GRID, PROP_BLK>>>(h1, 64, nullptr, 0, t1, 64);
    prop64<<<PROP_GRID, PROP_BLK>>>(t1, 64, nullptr, 0, t2, 64);
    gemm3_mma_kernel<64, 64, __half><<<GEMM_GRID, 256>>>(h1, t1, t2, W2, b2, h2);

    // ---- Layer 3 ----
    prop64<<<PROP_GRID, PROP_BLK>>>(h2, 64, nullptr, 0, t1, 64);
    prop64<<<PROP_GRID, PROP_BLK>>>(t1, 64, nullptr, 0, t2, 64);
    gemm3_mma_kernel<64, 40, float><<<GEMM_GRID, 256>>>(h2, t1, t2, W3, b3, out);
}

// round 13
// speedup vs baseline: 1.0001x; 1.0001x over previous
#include <cuda_runtime.h>
#include <cuda_fp16.h>
#include <cstdint>
#include <cstddef>

#define N_NODES 50000
#define N_EDGES 800000
#define CAP 96                          // bucket capacity per node (max in-deg ~38 expected)

// ---------------- scratch ----------------
__device__ int    g_deg[N_NODES];
__device__ float  g_norm[N_NODES];
__device__ int    g_bucket[N_NODES * CAP];   // 19.2 MB
__device__ __align__(16) __half g_xh[N_NODES * 128];   // fp16 features
__device__ __align__(16) __half g_Y[N_NODES * 192];    // layer-1 GEMM output (3 planes of 64)
__device__ __align__(16) __half g_t1h[N_NODES * 64];
__device__ __align__(16) __half g_t2h[N_NODES * 64];
__device__ __align__(16) __half g_h1h[N_NODES * 64];
__device__ __align__(16) __half g_h2h[N_NODES * 64];

// ---------------- feature convert ----------------
__global__ void cvt_kernel(const float* __restrict__ X) {
    int i = blockIdx.x * blockDim.x + threadIdx.x;   // over half2 pairs
    if (i < N_NODES * 64) {
        float2 v = ((const float2*)X)[i];
        ((__half2*)g_xh)[i] = __float22half2_rn(v);
    }
}

// ---------------- graph build: single edge pass into buckets ----------------
__global__ void zero_deg_kernel() {
    int i = blockIdx.x * blockDim.x + threadIdx.x;
    if (i < N_NODES) g_deg[i] = 0;
}

__global__ void fill_bucket_kernel(const int* __restrict__ src, const int* __restrict__ dst) {
    int i = blockIdx.x * blockDim.x + threadIdx.x;   // groups of 4 edges
    if (i * 4 + 4 <= N_EDGES) {
        int4 d = ((const int4*)dst)[i];
        int4 s = ((const int4*)src)[i];
        int p0 = atomicAdd(&g_deg[d.x], 1);
        int p1 = atomicAdd(&g_deg[d.y], 1);
        int p2 = atomicAdd(&g_deg[d.z], 1);
        int p3 = atomicAdd(&g_deg[d.w], 1);
        if (p0 < CAP) g_bucket[d.x * CAP + p0] = s.x;
        if (p1 < CAP) g_bucket[d.y * CAP + p1] = s.y;
        if (p2 < CAP) g_bucket[d.z * CAP + p2] = s.z;
        if (p3 < CAP) g_bucket[d.w * CAP + p3] = s.w;
    }
}

__global__ void norm_kernel() {
    int i = blockIdx.x * blockDim.x + threadIdx.x;
    if (i < N_NODES) {
        float d = (float)g_deg[i];
        g_norm[i] = rsqrtf(d < 1.0f ? 1.0f : d);
    }
}

// ---------------- propagation (64 cols, 4 nodes/warp, fully predicated 8-edge loop) ----------------
// out[n] = (addt ? addt[n] : 0) + norm[n] * sum_{e in in(n)} X[src_e]*norm[src_e]
__global__ void prop64(const __half* __restrict__ X, int sx,
                       const __half* __restrict__ addt, int sa,
                       __half* __restrict__ out, int so) {
    int gwarp = (blockIdx.x * blockDim.x + threadIdx.x) >> 5;
    int lane = threadIdx.x & 31;
    int node = gwarp * 4 + (lane >> 3);
    int sub  = lane & 7;
    if (node >= N_NODES) return;
    int dg = g_deg[node];
    if (dg > CAP) dg = CAP;
    const int* bkt = g_bucket + node * CAP;

    float acc[8];
    #pragma unroll
    for (int i = 0; i < 8; i++) acc[i] = 0.f;

    for (int e = 0; e < dg; e += 8) {
        int s[8];
        float nn[8];
        #pragma unroll
        for (int j = 0; j < 8; j++) {
            int idx = e + j;
            int cl = idx < dg ? idx : dg - 1;          // dg>=1 inside loop
            s[j] = bkt[cl];
            nn[j] = idx < dg ? g_norm[s[j]] : 0.f;     // zero-weight OOB
        }
        uint4 v[8];
        #pragma unroll
        for (int j = 0; j < 8; j++)
            v[j] = *(const uint4*)(X + (size_t)s[j] * sx + sub * 8);
        #pragma unroll
        for (int j = 0; j < 8; j++) {
            float2 f0 = __half22float2(*(const __half2*)&v[j].x);
            float2 f1 = __half22float2(*(const __half2*)&v[j].y);
            float2 f2 = __half22float2(*(const __half2*)&v[j].z);
            float2 f3 = __half22float2(*(const __half2*)&v[j].w);
            acc[0] += f0.x * nn[j]; acc[1] += f0.y * nn[j];
            acc[2] += f1.x * nn[j]; acc[3] += f1.y * nn[j];
            acc[4] += f2.x * nn[j]; acc[5] += f2.y * nn[j];
            acc[6] += f3.x * nn[j]; acc[7] += f3.y * nn[j];
        }
    }

    float m = g_norm[node];
    float r[8];
    #pragma unroll
    for (int i = 0; i < 8; i++) r[i] = m * acc[i];
    if (addt) {
        uint4 a = *(const uint4*)(addt + (size_t)node * sa + sub * 8);
        float2 f0 = __half22float2(*(const __half2*)&a.x);
        float2 f1 = __half22float2(*(const __half2*)&a.y);
        float2 f2 = __half22float2(*(const __half2*)&a.z);
        float2 f3 = __half22float2(*(const __half2*)&a.w);
        r[0] += f0.x; r[1] += f0.y; r[2] += f1.x; r[3] += f1.y;
        r[4] += f2.x; r[5] += f2.y; r[6] += f3.x; r[7] += f3.y;
    }
    uint4 w;
    *(__half2*)&w.x = __floats2half2_rn(r[0], r[1]);
    *(__half2*)&w.y = __floats2half2_rn(r[2], r[3]);
    *(__half2*)&w.z = __floats2half2_rn(r[4], r[5]);
    *(__half2*)&w.w = __floats2half2_rn(r[6], r[7]);
    *(uint4*)(out + (size_t)node * so + sub * 8) = w;
}

// ---------------- mma helper ----------------
__device__ __forceinline__ void mma_f16(float* c, const uint32_t* a, uint32_t b0, uint32_t b1) {
    asm volatile(
        "mma.sync.aligned.m16n8k16.row.col.f32.f16.f16.f32 "
        "{%0,%1,%2,%3}, {%4,%5,%6,%7}, {%8,%9}, {%0,%1,%2,%3};"
        : "+f"(c[0]), "+f"(c[1]), "+f"(c[2]), "+f"(c[3])
        : "r"(a[0]), "r"(a[1]), "r"(a[2]), "r"(a[3]), "r"(b0), "r"(b1));
}

// ---------------- Layer-1 commuted GEMM: Y[50k,192] = X @ foldW ----------------
// blockIdx.y = plane (0: W0-W2 +bias, 1: -W1, 2: 2*W2); 64 cols per plane → NT=8.
template <int F, int FTOT>
__global__ void gemmY_kernel(const __half* __restrict__ X,
                             const float* __restrict__ W,      // [3F, 64]
                             const float* __restrict__ bias,   // [64]
                             __half* __restrict__ Y) {
    constexpr int NT  = 8;
    constexpr int LDK = F + 2;
    __shared__ alignas(16) __half Ws[64 * LDK];   // Ws[col_local][k]

    int tid  = threadIdx.x;
    int warp = tid >> 5;
    int lane = tid & 31;
    int grp  = lane >> 2;
    int qid  = lane & 3;
    int plane = blockIdx.y;
    int colbase = plane * 64;
    int r0 = blockIdx.x * 256 + warp * 32;

    for (int i = tid; i < 64 * F; i += 256) {
        int k  = i / 64;
        int cc = i - k * 64;
        float v;
        if (plane == 0)      v = W[k * 64 + cc] - W[(2 * F + k) * 64 + cc];
        else if (plane == 1) v = -W[(F + k) * 64 + cc];
        else                 v = 2.0f * W[(2 * F + k) * 64 + cc];
        Ws[cc * LDK + k] = __float2half_rn(v);
    }
    __syncthreads();

    float c[2][NT][4];
    #pragma unroll
    for (int t = 0; t < 2; t++)
        #pragma unroll
        for (int n = 0; n < NT; n++)
            #pragma unroll
            for (int j = 0; j < 4; j++) c[t][n][j] = 0.f;

    int ra0 = r0 + grp;       if (ra0 >= N_NODES) ra0 = N_NODES - 1;
    int ra1 = r0 + grp + 8;   if (ra1 >= N_NODES) ra1 = N_NODES - 1;
    int ra2 = r0 + grp + 16;  if (ra2 >= N_NODES) ra2 = N_NODES - 1;
    int ra3 = r0 + grp + 24;  if (ra3 >= N_NODES) ra3 = N_NODES - 1;
    const __half* p0 = X + (size_t)ra0 * F;
    const __half* p1 = X + (size_t)ra1 * F;
    const __half* p2 = X + (size_t)ra2 * F;
    const __half* p3 = X + (size_t)ra3 * F;

    for (int k0 = 0; k0 < F; k0 += 16) {
        int ka = k0 + 2 * qid;
        uint32_t A0[4], A1[4];
        A0[0] = *(const uint32_t*)(p0 + ka);
        A0[1] = *(const uint32_t*)(p1 + ka);
        A0[2] = *(const uint32_t*)(p0 + ka + 8);
        A0[3] = *(const uint32_t*)(p1 + ka + 8);
        A1[0] = *(const uint32_t*)(p2 + ka);
        A1[1] = *(const uint32_t*)(p3 + ka);
        A1[2] = *(const uint32_t*)(p2 + ka + 8);
        A1[3] = *(const uint32_t*)(p3 + ka + 8);

        #pragma unroll
        for (int n = 0; n < NT; n++) {
            const __half* wb = Ws + (n * 8 + grp) * LDK + ka;
            uint32_t b0 = *(const uint32_t*)(wb);
            uint32_t b1 = *(const uint32_t*)(wb + 8);
            mma_f16(c[0][n], A0, b0, b1);
            mma_f16(c[1][n], A1, b0, b1);
        }
    }

    #pragma unroll
    for (int t = 0; t < 2; t++) {
        int rA = r0 + t * 16 + grp;
        int rB = rA + 8;
        #pragma unroll
        for (int n = 0; n < NT; n++) {
            int cl = n * 8 + qid * 2;
            float bx = (plane == 0) ? bias[cl] : 0.f;
            float by = (plane == 0) ? bias[cl + 1] : 0.f;
            int col = colbase + cl;
            if (rA < N_NODES) {
                __half2 v = __floats2half2_rn(c[t][n][0] + bx, c[t][n][1] + by);
                *(__half2*)(Y + (size_t)rA * FTOT + col) = v;
            }
            if (rB < N_NODES) {
                __half2 v = __floats2half2_rn(c[t][n][2] + bx, c[t][n][3] + by);
                *(__half2*)(Y + (size_t)rB * FTOT + col) = v;
            }
        }
    }
}

// ---------------- 3-input GEMM (layers 2,3) ----------------
template <int F, int FOUT, typename OutT>
__global__ void gemm3_mma_kernel(const __half* __restrict__ X0,
                                 const __half* __restrict__ X1,
                                 const __half* __restrict__ X2,
                                 const float* __restrict__ W,
                                 const float* __restrict__ bias,
                                 OutT* __restrict__ out) {
    constexpr int NT  = FOUT / 8;
    constexpr int LDK = F + 2;
    __shared__ alignas(16) __half Ws[FOUT * LDK];

    int tid  = threadIdx.x;
    int warp = tid >> 5;
    int lane = tid & 31;
    int grp  = lane >> 2;
    int qid  = lane & 3;
    int r0 = blockIdx.x * 256 + warp * 32;

    float c[2][NT][4];
    #pragma unroll
    for (int t = 0; t < 2; t++)
        #pragma unroll
        for (int n = 0; n < NT; n++)
            #pragma unroll
            for (int j = 0; j < 4; j++) c[t][n][j] = 0.f;

    const __half* segs[3] = {X0, X1, X2};

    int ra0 = r0 + grp;       if (ra0 >= N_NODES) ra0 = N_NODES - 1;
    int ra1 = r0 + grp + 8;   if (ra1 >= N_NODES) ra1 = N_NODES - 1;
    int ra2 = r0 + grp + 16;  if (ra2 >= N_NODES) ra2 = N_NODES - 1;
    int ra3 = r0 + grp + 24;  if (ra3 >= N_NODES) ra3 = N_NODES - 1;

    #pragma unroll
    for (int seg = 0; seg < 3; ++seg) {
        __syncthreads();
        for (int i = tid; i < F * FOUT; i += 256) {
            int k = i / FOUT, col = i - k * FOUT;
            float v;
            if (seg == 0)      v = W[i] - W[2 * F * FOUT + i];
            else if (seg == 1) v = -W[F * FOUT + i];
            else               v = 2.0f * W[2 * F * FOUT + i];
            Ws[col * LDK + k] = __float2half_rn(v);
        }
        __syncthreads();

        const __half* X  = segs[seg];
        const __half* p0 = X + (size_t)ra0 * F;
        const __half* p1 = X + (size_t)ra1 * F;
        const __half* p2 = X + (size_t)ra2 * F;
        const __half* p3 = X + (size_t)ra3 * F;

        for (int k0 = 0; k0 < F; k0 += 16) {
            int ka = k0 + 2 * qid;
            uint32_t A0[4], A1[4];
            A0[0] = *(const uint32_t*)(p0 + ka);
            A0[1] = *(const uint32_t*)(p1 + ka);
            A0[2] = *(const uint32_t*)(p0 + ka + 8);
            A0[3] = *(const uint32_t*)(p1 + ka + 8);
            A1[0] = *(const uint32_t*)(p2 + ka);
            A1[1] = *(const uint32_t*)(p3 + ka);
            A1[2] = *(const uint32_t*)(p2 + ka + 8);
            A1[3] = *(const uint32_t*)(p3 + ka + 8);

            #pragma unroll
            for (int n = 0; n < NT; n++) {
                const __half* wb = Ws + (n * 8 + grp) * LDK + ka;
                uint32_t b0 = *(const uint32_t*)(wb);
                uint32_t b1 = *(const uint32_t*)(wb + 8);
                mma_f16(c[0][n], A0, b0, b1);
                mma_f16(c[1][n], A1, b0, b1);
            }
        }
    }

    #pragma unroll
    for (int t = 0; t < 2; t++) {
        int rA = r0 + t * 16 + grp;
        int rB = rA + 8;
        #pragma unroll
        for (int n = 0; n < NT; n++) {
            int col = n * 8 + qid * 2;
            float bx = bias[col], by = bias[col + 1];
            if (rA < N_NODES) {
                if constexpr (sizeof(OutT) == 2) {
                    __half2 v = __floats2half2_rn(c[t][n][0] + bx, c[t][n][1] + by);
                    *(__half2*)((__half*)out + (size_t)rA * FOUT + col) = v;
                } else {
                    float2 v = make_float2(c[t][n][0] + bx, c[t][n][1] + by);
                    *(float2*)((float*)out + (size_t)rA * FOUT + col) = v;
                }
            }
            if (rB < N_NODES) {
                if constexpr (sizeof(OutT) == 2) {
                    __half2 v = __floats2half2_rn(c[t][n][2] + bx, c[t][n][3] + by);
                    *(__half2*)((__half*)out + (size_t)rB * FOUT + col) = v;
                } else {
                    float2 v = make_float2(c[t][n][2] + bx, c[t][n][3] + by);
                    *(float2*)((float*)out + (size_t)rB * FOUT + col) = v;
                }
            }
        }
    }
}

// ---------------- host ----------------
extern "C" void kernel_launch(void* const* d_in, const int* in_sizes, int n_in,
                              void* d_out, int out_size) {
    const float* features = (const float*)d_in[0];   // [50000,128]
    const int*   src      = (const int*)d_in[1];     // [800000]
    const int*   dst      = (const int*)d_in[2];     // [800000]
    const float* W1       = (const float*)d_in[3];   // [384,64]
    const float* b1       = (const float*)d_in[4];   // [64]
    const float* W2       = (const float*)d_in[5];   // [192,64]
    const float* b2       = (const float*)d_in[6];   // [64]
    const float* W3       = (const float*)d_in[7];   // [192,40]
    const float* b3       = (const float*)d_in[8];   // [40]
    float* out            = (float*)d_out;           // [50000,40]

    __half *xh, *Y, *t1, *t2, *h1, *h2;
    cudaGetSymbolAddress((void**)&xh, g_xh);
    cudaGetSymbolAddress((void**)&Y,  g_Y);
    cudaGetSymbolAddress((void**)&t1, g_t1h);
    cudaGetSymbolAddress((void**)&t2, g_t2h);
    cudaGetSymbolAddress((void**)&h1, g_h1h);
    cudaGetSymbolAddress((void**)&h2, g_h2h);

    static cudaStream_t sB = nullptr;
    static cudaEvent_t evFork = nullptr, evJoin = nullptr;
    if (!sB) {
        cudaStreamCreateWithFlags(&sB, cudaStreamNonBlocking);
        cudaEventCreateWithFlags(&evFork, cudaEventDisableTiming);
        cudaEventCreateWithFlags(&evJoin, cudaEventDisableTiming);
    }

    const int PROP_BLK  = 256;                        // 8 warps x 4 nodes = 32 nodes/block
    const int PROP_GRID = (N_NODES + 31) / 32;
    const int GEMM_GRID = (N_NODES + 255) / 256;

    // ---- fork: bucket build on sB, cvt+gemmY on main stream ----
    cudaEventRecord(evFork, 0);
    cudaStreamWaitEvent(sB, evFork, 0);

    zero_deg_kernel<<<(N_NODES + 255) / 256, 256, 0, sB>>>();
    fill_bucket_kernel<<<(N_EDGES / 4 + 255) / 256, 256, 0, sB>>>(src, dst);
    norm_kernel<<<(N_NODES + 255) / 256, 256, 0, sB>>>();
    cudaEventRecord(evJoin, sB);

    cvt_kernel<<<(N_NODES * 64 + 255) / 256, 256>>>(features);
    {
        dim3 grid(GEMM_GRID, 3);                      // 3 planes of 64 cols
        gemmY_kernel<128, 192><<<grid, 256>>>(xh, W1, b1, Y);
    }
    cudaStreamWaitEvent(0, evJoin, 0);

    // ---- Layer 1 (commuted): t1 = Y1 + P Y2; h1 = Y0 + P t1 ----
    prop64<<<PROP_GRID, PROP_BLK>>>(Y + 128, 192, Y + 64, 192, t1, 64);
    prop64<<<PROP_GRID, PROP_BLK>>>(t1, 64, Y, 192, h1, 64);

    // ---- Layer 2: U1 = P h1, U2 = P U1; gemm3 folded ----
    prop64<<<PROP_GRID, PROP_BLK>>>(h1, 64, nullptr, 0, t1, 64);
    prop64<<<PROP_GRID, PROP_BLK>>>(t1, 64, nullptr, 0, t2, 64);
    gemm3_mma_kernel<64, 64, __half><<<GEMM_GRID, 256>>>(h1, t1, t2, W2, b2, h2);

    // ---- Layer 3 ----
    prop64<<<PROP_GRID, PROP_BLK>>>(h2, 64, nullptr, 0, t1, 64);
    prop64<<<PROP_GRID, PROP_BLK>>>(t1, 64, nullptr, 0, t2, 64);
    gemm3_mma_kernel<64, 40, float><<<GEMM_GRID, 256>>>(h2, t1, t2, W3, b3, out);
}